// round 17
// baseline (speedup 1.0000x reference)
#include <cuda_runtime.h>
#include <cuda_fp16.h>
#include <math.h>

// Problem shape (fixed): B=8, C=4, H=256, W=256, labels in [0,4)
#define B 8
#define H 256
#define W 256
#define NPIX (B * H * W)          // 524288
#define NROWS (B * H)             // 2048
#define NBLK4 (NROWS / 4)         // 512 k_horiz blocks (4 rows each)
#define DENOM 2097152.0           // B*C*H*W
#define FPSCALE 16777216.0        // 2^24 fixed-point scale
#define HBIG 65504.0f             // half max: absent-class sentinel

// Scratch: per-pixel uint2 = two half2 = per-class vertical d^2 (half).
__device__ uint2 g_G[NPIX];
__device__ unsigned long long g_acc;         // fixed-point loss accumulator (zero-init)
__device__ unsigned int g_count;             // completed-block counter (zero-init)

__device__ __forceinline__ float fsqrt_fast(float v)
{
    float r;
    asm("sqrt.approx.f32 %0, %1;" : "=f"(r) : "f"(v));
    return r;
}

// ---------------------------------------------------------------------------
// K1: vertical EDT via per-column class bitmasks (round-10 version, measured
// ~4 us). 256 blocks x 256 threads; 8 columns per block, 8 rows per thread.
// PDL: triggers the dependent k_horiz launch immediately so k_horiz's
// g_G-independent prologue overlaps this kernel's execution.
// ---------------------------------------------------------------------------
__global__ void __launch_bounds__(256) k_vert(const int* __restrict__ y)
{
    cudaTriggerProgrammaticLaunchCompletion();

    __shared__ unsigned msk[4 * 8 * 8];      // [c][col][word] = c*64+col*8+word

    const int b    = blockIdx.x >> 5;        // 256 blocks: 8 b * 32 w-tiles
    const int w0   = (blockIdx.x & 31) << 3; // 8 columns per block
    const int tid  = threadIdx.x;            // 256 threads = 8 warps
    const int warp = tid >> 5;               // = mask word index (row/32)
    const int lane = tid & 31;

    // --- phase 1: build occupancy masks with ballots ---
    {
        const int row = warp * 32 + lane;
        const int* yrow = y + b * (H * W) + row * W + w0;
        int4 va = *(const int4*)yrow;
        int4 vb = *(const int4*)(yrow + 4);
        int lab[8] = {va.x, va.y, va.z, va.w, vb.x, vb.y, vb.z, vb.w};

        unsigned myword = 0;
        #pragma unroll
        for (int c = 0; c < 4; ++c) {
            #pragma unroll
            for (int k = 0; k < 8; ++k) {
                unsigned bal = __ballot_sync(0xffffffffu, lab[k] == c);
                if (lane == ((c << 3) | k)) myword = bal;
            }
        }
        msk[(lane >> 3) * 64 + (lane & 7) * 8 + warp] = myword;
    }
    __syncthreads();

    // --- phase 2: per-thread distance computation (8 rows x 1 col) ---
    const int col = tid & 7;
    const int h0  = (tid >> 3) << 3;         // 0,8,...,248
    const int wi  = h0 >> 5;                 // constant word for rows h0..h0+7
    const int hb  = h0 & 31;                 // 0,8,16,24

    unsigned resx[8], resy[8];
    float fa[8];

    #pragma unroll
    for (int c = 0; c < 4; ++c) {
        const unsigned* base = &msk[c * 64 + col * 8];
        const unsigned Mw = base[wi];

        // init_down: nearest set bit <= h0-1
        int last = -1000;
        {
            unsigned bits = hb ? (Mw & ((1u << hb) - 1u)) : 0u;
            if (bits) {
                last = wi * 32 + 31 - __clz(bits);
            } else {
                for (int wj = wi - 1; wj >= 0; --wj) {
                    unsigned m2 = base[wj];
                    if (m2) { last = wj * 32 + 31 - __clz(m2); break; }
                }
            }
        }
        // init_up: nearest set bit >= h0+8
        int nxt = 100000;
        {
            int rem = hb + 8;
            unsigned bits = (rem < 32) ? (Mw >> rem) : 0u;
            if (bits) {
                nxt = wi * 32 + rem + __ffs(bits) - 1;
            } else {
                for (int wj = wi + 1; wj < 8; ++wj) {
                    unsigned m2 = base[wj];
                    if (m2) { nxt = wj * 32 + __ffs(m2) - 1; break; }
                }
            }
        }

        int dd[8];
        #pragma unroll
        for (int i = 0; i < 8; ++i) {
            int h = h0 + i;
            if ((Mw >> (h & 31)) & 1u) last = h;
            dd[i] = h - last;
        }
        #pragma unroll
        for (int i = 7; i >= 0; --i) {
            int h = h0 + i;
            if ((Mw >> (h & 31)) & 1u) nxt = h;
            int du = nxt - h;
            int d = min(dd[i], du);
            float f = (d > 255) ? HBIG : (float)(d * d);
            if (c == 0)      fa[i] = f;
            else if (c == 1) {
                __half2 p = __floats2half2_rn(fa[i], f);
                resx[i] = *reinterpret_cast<unsigned*>(&p);
            }
            else if (c == 2) fa[i] = f;
            else {
                __half2 p = __floats2half2_rn(fa[i], f);
                resy[i] = *reinterpret_cast<unsigned*>(&p);
            }
        }
    }

    uint2* Gb = g_G + b * (H * W) + w0 + col;
    #pragma unroll
    for (int i = 0; i < 8; ++i)
        Gb[(h0 + i) * W] = make_uint2(resx[i], resy[i]);
}

// ---------------------------------------------------------------------------
// K2: horizontal min-plus, FOUR ROWS PER BLOCK (round-16 version, measured
// 10.98 us) + PDL: x/y loads and pad-init run BEFORE the grid dependency
// sync, overlapping k_vert; g_G is only touched after the sync.
// ---------------------------------------------------------------------------
__global__ void __launch_bounds__(256) k_horiz(const float* __restrict__ x,
                                               const int* __restrict__ y,
                                               float* __restrict__ out)
{
    const int row0 = blockIdx.x * 4;   // rows row0..row0+3 (same image: 256%4==0)
    const int b    = row0 >> 8;
    const int h0r  = row0 & 255;
    const int tid  = threadIdx.x;      // 0..255, w = tid
    const int wid  = tid >> 5, lane = tid & 31;

    __shared__ uint2 sgp[4][768];      // per row: [pad 256][data 256][pad 256]

    // g_G-independent prologue: overlaps k_vert under PDL
    int   yv[4];
    float lx[4][4];
    const int base = (b * 4) * (H * W) + h0r * W + tid;
    #pragma unroll
    for (int r = 0; r < 4; ++r) {
        yv[r] = y[(row0 + r) * W + tid];
        #pragma unroll
        for (int c = 0; c < 4; ++c)
            lx[r][c] = x[base + r * W + c * (H * W)];
    }

    const uint2 big = make_uint2(0x7BFF7BFFu, 0x7BFF7BFFu);  // half2(65504) x2
    #pragma unroll
    for (int r = 0; r < 4; ++r) {
        sgp[r][tid] = big;                       // left pad
        sgp[r][512 + tid] = big;                 // right pad
    }

    // wait for k_vert's g_G writes (no-op if launched without PDL)
    cudaGridDependencySynchronize();

    #pragma unroll
    for (int r = 0; r < 4; ++r)
        sgp[r][256 + tid] = g_G[(row0 + r) * W + tid];
    __syncthreads();

    __half2 ba[4], bb[4];
    #pragma unroll
    for (int r = 0; r < 4; ++r) {
        uint2 q = sgp[r][256 + tid];
        ba[r] = *reinterpret_cast<__half2*>(&q.x);
        bb[r] = *reinterpret_cast<__half2*>(&q.y);
    }

    for (int off0 = 1; off0 < 256; off0 += 4) {
        #pragma unroll
        for (int u = 0; u < 4; ++u) {
            int off = off0 + u;                      // max 256 -> within pads
            __half2 o2 = __float2half2_rn((float)(off * off));
            #pragma unroll
            for (int r = 0; r < 4; ++r) {
                uint2 l = sgp[r][256 + tid - off];
                uint2 rr = sgp[r][256 + tid + off];
                __half2 la = *reinterpret_cast<__half2*>(&l.x);
                __half2 lb = *reinterpret_cast<__half2*>(&l.y);
                __half2 ra = *reinterpret_cast<__half2*>(&rr.x);
                __half2 rb = *reinterpret_cast<__half2*>(&rr.y);
                ba[r] = __hmin2(ba[r], __hadd2(o2, __hmin2(la, ra)));
                bb[r] = __hmin2(bb[r], __hadd2(o2, __hmin2(lb, rb)));
            }
        }
        float nxt = (float)((off0 + 4) * (off0 + 4));
        __half2 m2 = __hmax2(__hmax2(ba[0], bb[0]), __hmax2(ba[1], bb[1]));
        __half2 m3 = __hmax2(__hmax2(ba[2], bb[2]), __hmax2(ba[3], bb[3]));
        m2 = __hmax2(m2, m3);
        float mb = fmaxf(__low2float(m2), __high2float(m2));
        if (!__any_sync(0xffffffffu, nxt < mb)) break;
    }

    float acc = 0.0f;
    #pragma unroll
    for (int r = 0; r < 4; ++r) {
        float b0 = __low2float(ba[r]), b1 = __high2float(ba[r]);
        float b2 = __low2float(bb[r]), b3 = __high2float(bb[r]);
        float n0 = fminf(fminf(b1, b2), b3);
        float n1 = fminf(fminf(b0, b2), b3);
        float n2 = fminf(fminf(b0, b1), b3);
        float n3 = fminf(fminf(b0, b1), b2);
        float mx = fmaxf(fmaxf(lx[r][0], lx[r][1]), fmaxf(lx[r][2], lx[r][3]));
        float e0 = __expf(lx[r][0] - mx), e1 = __expf(lx[r][1] - mx);
        float e2 = __expf(lx[r][2] - mx), e3 = __expf(lx[r][3] - mx);
        float s = e0 + e1 + e2 + e3;
        float d0 = (yv[r] == 0) ? -fsqrt_fast(n0) : fsqrt_fast(b0);
        float d1 = (yv[r] == 1) ? -fsqrt_fast(n1) : fsqrt_fast(b1);
        float d2 = (yv[r] == 2) ? -fsqrt_fast(n2) : fsqrt_fast(b2);
        float d3 = (yv[r] == 3) ? -fsqrt_fast(n3) : fsqrt_fast(b3);
        acc += __fdividef(e0 * d0 + e1 * d1 + e2 * d2 + e3 * d3, s);
    }

    // warp-shuffle reduction (fixed order -> deterministic)
    #pragma unroll
    for (int o = 16; o > 0; o >>= 1)
        acc += __shfl_down_sync(0xffffffffu, acc, o);

    __shared__ float swsum[8];
    if (lane == 0) swsum[wid] = acc;
    __syncthreads();

    if (wid == 0) {
        float v = (lane < 8) ? swsum[lane] : 0.0f;
        #pragma unroll
        for (int o = 4; o > 0; o >>= 1)
            v += __shfl_down_sync(0xffffffffu, v, o);

        if (lane == 0) {
            long long fx = llrintf(v * (float)FPSCALE);
            atomicAdd(&g_acc, (unsigned long long)fx);
            __threadfence();
            unsigned int done = atomicAdd(&g_count, 1u);
            if (done == NBLK4 - 1) {
                unsigned long long total = atomicAdd(&g_acc, 0ULL);
                out[0] = (float)((double)(long long)total / (FPSCALE * DENOM));
                g_acc = 0ULL;          // self-reset for next graph replay
                g_count = 0u;
                __threadfence();
            }
        }
    }
}

extern "C" void kernel_launch(void* const* d_in, const int* in_sizes, int n_in,
                              void* d_out, int out_size)
{
    const float* x;
    const int*   y;
    if (in_sizes[0] == NPIX * 4) {
        x = (const float*)d_in[0];
        y = (const int*)d_in[1];
    } else {
        x = (const float*)d_in[1];
        y = (const int*)d_in[0];
    }
    float* out = (float*)d_out;

    k_vert<<<256, 256>>>(y);

    // k_horiz with programmatic dependent launch (overlap prologue with
    // k_vert); fall back to a plain launch if the attribute is rejected.
    cudaLaunchConfig_t cfg = {};
    cfg.gridDim = dim3(NBLK4);
    cfg.blockDim = dim3(256);
    cfg.dynamicSmemBytes = 0;
    cfg.stream = 0;
    cudaLaunchAttribute attrs[1];
    attrs[0].id = cudaLaunchAttributeProgrammaticStreamSerialization;
    attrs[0].val.programmaticStreamSerializationAllowed = 1;
    cfg.attrs = attrs;
    cfg.numAttrs = 1;
    if (cudaLaunchKernelEx(&cfg, k_horiz, x, y, out) != cudaSuccess)
        k_horiz<<<NBLK4, 256>>>(x, y, out);
}